// round 2
// baseline (speedup 1.0000x reference)
#include <cuda_runtime.h>
#include <cuda_bf16.h>
#include <cstdint>

#define DT_STEP 0.01f
#define ROW_B 272                       // smem row: 128 bf16 (256B) + 16B pad
#define S_AHI 0
#define S_ALO (S_AHI + 128 * ROW_B)
#define S_W   (S_ALO + 128 * ROW_B)
#define S_H   (S_W   + 128 * ROW_B)
#define S_B1  (S_H   + 128 * ROW_B)
#define S_B2  (S_B1 + 512)
#define S_TOT (S_B2 + 512)              // 140288 B -> 1 CTA/SM

// ---------------- helpers ----------------
static __device__ __forceinline__ uint32_t smem_u32(const void* p) {
    uint32_t a;
    asm("{ .reg .u64 t; cvta.to.shared.u64 t, %1; cvt.u32.u64 %0, t; }" : "=r"(a) : "l"(p));
    return a;
}

static __device__ __forceinline__ uint32_t packbf(float a, float b) {
    __nv_bfloat162 t = __floats2bfloat162_rn(a, b);   // .x = a in low 16 bits
    return *reinterpret_cast<uint32_t*>(&t);
}

static __device__ __forceinline__ void split2(float a, float b, uint32_t& hi, uint32_t& lo) {
    float ah = __bfloat162float(__float2bfloat16_rn(a));
    float bh = __bfloat162float(__float2bfloat16_rn(b));
    hi = packbf(a, b);
    lo = packbf(a - ah, b - bh);
}

static __device__ __forceinline__ __nv_bfloat162 u2bf(uint32_t v) {
    return *reinterpret_cast<__nv_bfloat162*>(&v);
}

static __device__ __forceinline__ float tanh_fast(float v) {
    float r;
    asm("tanh.approx.f32 %0, %1;" : "=f"(r) : "f"(v));
    return r;
}

static __device__ __forceinline__ void ldsm_x4(uint32_t* r, uint32_t addr) {
    asm volatile("ldmatrix.sync.aligned.m8n8.x4.shared.b16 {%0,%1,%2,%3}, [%4];"
                 : "=r"(r[0]), "=r"(r[1]), "=r"(r[2]), "=r"(r[3]) : "r"(addr));
}

static __device__ __forceinline__ void ldsm_x4_t(uint32_t* r, uint32_t addr) {
    asm volatile("ldmatrix.sync.aligned.m8n8.x4.trans.shared.b16 {%0,%1,%2,%3}, [%4];"
                 : "=r"(r[0]), "=r"(r[1]), "=r"(r[2]), "=r"(r[3]) : "r"(addr));
}

static __device__ __forceinline__ void mma16816(float* d, const uint32_t* a, const uint32_t* b) {
    asm volatile("mma.sync.aligned.m16n8k16.row.col.f32.bf16.bf16.f32 "
                 "{%0,%1,%2,%3}, {%4,%5,%6,%7}, {%8,%9}, {%0,%1,%2,%3};"
                 : "+f"(d[0]), "+f"(d[1]), "+f"(d[2]), "+f"(d[3])
                 : "r"(a[0]), "r"(a[1]), "r"(a[2]), "r"(a[3]), "r"(b[0]), "r"(b[1]));
}

// One warp computes a 16x128 output tile: A rows [mbase,mbase+16), all 128 N.
// A: smem row-major [128][ROW_B], bf16, k contiguous. W: smem row-major [k][n] bf16.
static __device__ __forceinline__ void gemm_tile(uint32_t abase, uint32_t wbase,
                                                 int lane, float acc[16][4]) {
    uint32_t afr[8][4];
    // A-frag lane address: m0=(r0-7,k0-7) m1=(r8-15,k0-7) m2=(r0-7,k8-15) m3=(r8-15,k8-15)
    uint32_t arow = abase + (uint32_t)((lane & 7) + ((lane >> 3) & 1) * 8) * ROW_B
                  + (uint32_t)(lane >> 4) * 16;
    #pragma unroll
    for (int kt = 0; kt < 8; kt++) ldsm_x4(afr[kt], arow + kt * 32);

    uint32_t wl = wbase + (uint32_t)lane * ROW_B;   // lane supplies k-row addresses
    #pragma unroll
    for (int nt = 0; nt < 16; nt++) {
        uint32_t b[4][4];
        #pragma unroll
        for (int q = 0; q < 4; q++)
            ldsm_x4_t(b[q], wl + (uint32_t)q * (32 * ROW_B) + (uint32_t)nt * 16);
        #pragma unroll
        for (int kt = 0; kt < 8; kt++)
            mma16816(acc[nt], afr[kt], &b[kt >> 1][(kt & 1) * 2]);
    }
}

// ---------------- kernel ----------------
__global__ void __launch_bounds__(256, 1)
koopman_mma(const float* __restrict__ x, const float* __restrict__ W1,
            const float* __restrict__ b1, const float* __restrict__ W2,
            const float* __restrict__ b2, float* __restrict__ out)
{
    extern __shared__ char smem[];
    const uint32_t sb = smem_u32(smem);
    const int tid  = threadIdx.x;
    const int w    = tid >> 5;
    const int lane = tid & 31;
    const size_t row0 = (size_t)blockIdx.x * 128;

    if (tid < 128) {
        ((float*)(smem + S_B1))[tid] = b1[tid];
        ((float*)(smem + S_B2))[tid] = b2[tid];
    }

    // ---- stage x (bf16 hi/lo) + W1 (bf16), one warp per row, float4 loads ----
    #pragma unroll 4
    for (int it = 0; it < 16; it++) {
        int r = it * 8 + w;
        float4 v = *(const float4*)(x + (row0 + (size_t)r) * 128 + lane * 4);
        uint32_t h0, l0, h1, l1;
        split2(v.x, v.y, h0, l0);
        split2(v.z, v.w, h1, l1);
        *(uint2*)(smem + S_AHI + r * ROW_B + lane * 8) = make_uint2(h0, h1);
        *(uint2*)(smem + S_ALO + r * ROW_B + lane * 8) = make_uint2(l0, l1);
        float4 wv = *(const float4*)(W1 + (size_t)r * 128 + lane * 4);
        *(uint2*)(smem + S_W + r * ROW_B + lane * 8) =
            make_uint2(packbf(wv.x, wv.y), packbf(wv.z, wv.w));
    }
    __syncthreads();

    const int g  = lane >> 2;           // output row within 8-group
    const int t2 = (lane & 3) * 2;      // output col pair within 8-tile
    const int mbase = w * 16;

    // ---- GEMM1: pre = Xhi @ W1 ----
    float acc[16][4];
    #pragma unroll
    for (int i = 0; i < 16; i++)
        { acc[i][0] = 0.f; acc[i][1] = 0.f; acc[i][2] = 0.f; acc[i][3] = 0.f; }
    gemm_tile(sb + S_AHI + mbase * ROW_B, sb + S_W, lane, acc);
    __syncthreads();   // all warps done reading W1 before it is overwritten

    // ---- stage W2 into the same W buffer ----
    #pragma unroll 4
    for (int it = 0; it < 16; it++) {
        int r = it * 8 + w;
        float4 wv = *(const float4*)(W2 + (size_t)r * 128 + lane * 4);
        *(uint2*)(smem + S_W + r * ROW_B + lane * 8) =
            make_uint2(packbf(wv.x, wv.y), packbf(wv.z, wv.w));
    }

    // ---- epilogue 1: H = tanh(pre + b1) -> bf16 smem ----
    {
        const float* fb1 = (const float*)(smem + S_B1);
        const int r0 = mbase + g;
        #pragma unroll
        for (int nt = 0; nt < 16; nt++) {
            int c = nt * 8 + t2;
            float2 bb = *(const float2*)(fb1 + c);
            uint32_t p0 = packbf(tanh_fast(acc[nt][0] + bb.x), tanh_fast(acc[nt][1] + bb.y));
            uint32_t p1 = packbf(tanh_fast(acc[nt][2] + bb.x), tanh_fast(acc[nt][3] + bb.y));
            *(uint32_t*)(smem + S_H + r0 * ROW_B + c * 2) = p0;
            *(uint32_t*)(smem + S_H + (r0 + 8) * ROW_B + c * 2) = p1;
        }
    }
    __syncthreads();

    // ---- GEMM2: pre2 = H @ W2 ----
    #pragma unroll
    for (int i = 0; i < 16; i++)
        { acc[i][0] = 0.f; acc[i][1] = 0.f; acc[i][2] = 0.f; acc[i][3] = 0.f; }
    gemm_tile(sb + S_H + mbase * ROW_B, sb + S_W, lane, acc);

    // ---- epilogue 2: block-diagonal rotation-scaling on fp32-reconstructed x ----
    {
        const float* fb2 = (const float*)(smem + S_B2);
        #pragma unroll
        for (int nt = 0; nt < 16; nt++) {
            int c = nt * 8 + t2;
            float2 bb = *(const float2*)(fb2 + c);
            #pragma unroll
            for (int half = 0; half < 2; half++) {
                float mu = acc[nt][half * 2 + 0] + bb.x;
                float om = acc[nt][half * 2 + 1] + bb.y;
                int r = mbase + g + half * 8;
                uint32_t xh = *(const uint32_t*)(smem + S_AHI + r * ROW_B + c * 2);
                uint32_t xl = *(const uint32_t*)(smem + S_ALO + r * ROW_B + c * 2);
                __nv_bfloat162 hh = u2bf(xh), ll = u2bf(xl);
                float xe = __low2float(hh)  + __low2float(ll);
                float xo = __high2float(hh) + __high2float(ll);
                // exp(z), cos(wv), sin(wv) for |z|,|wv| <~ 0.05: short polynomials
                float z = DT_STEP * mu;
                float e = fmaf(z, fmaf(z, fmaf(z, 1.f / 6.f, 0.5f), 1.f), 1.f);
                float wv = DT_STEP * om;
                float w2 = wv * wv;
                float s = wv * fmaf(w2, -1.f / 6.f, 1.f);
                float cc = fmaf(w2, fmaf(w2, 1.f / 24.f, -0.5f), 1.f);
                float2 o;
                o.x = e * (cc * xe - s * xo);
                o.y = e * (s * xe + cc * xo);
                *(float2*)(out + (row0 + (size_t)r) * 128 + c) = o;
            }
        }
    }
}

// ---------------- launch ----------------
extern "C" void kernel_launch(void* const* d_in, const int* in_sizes, int n_in,
                              void* d_out, int out_size) {
    const float* x  = (const float*)d_in[0];
    const float* W1 = (const float*)d_in[1];
    const float* b1 = (const float*)d_in[2];
    const float* W2 = (const float*)d_in[3];
    const float* b2 = (const float*)d_in[4];
    float* out = (float*)d_out;

    int batch  = in_sizes[0] / 128;   // 131072
    int blocks = batch / 128;         // 1024

    cudaFuncSetAttribute(koopman_mma,
                         cudaFuncAttributeMaxDynamicSharedMemorySize, S_TOT);
    koopman_mma<<<blocks, 256, S_TOT>>>(x, W1, b1, W2, b2, out);
}

// round 3
// speedup vs baseline: 1.5367x; 1.5367x over previous
#include <cuda_runtime.h>
#include <cuda_bf16.h>
#include <cstdint>

#define DT_STEP 0.01f
#define NUM_TILES 1024
#define GRID_SMS 152
#define ROW_B 272                       // 128 bf16 (256B) + 16B pad
#define S_W1  0
#define S_W2  (S_W1 + 128 * ROW_B)
#define S_AHI (S_W2 + 128 * ROW_B)
#define S_ALO (S_AHI + 128 * ROW_B)
#define S_H   (S_ALO + 128 * ROW_B)
#define S_B1  (S_H   + 128 * ROW_B)
#define S_B2  (S_B1 + 512)
#define S_TOT (S_B2 + 512)              // 175104 B -> 1 CTA/SM

// ---------------- helpers ----------------
static __device__ __forceinline__ uint32_t smem_u32(const void* p) {
    uint32_t a;
    asm("{ .reg .u64 t; cvta.to.shared.u64 t, %1; cvt.u32.u64 %0, t; }" : "=r"(a) : "l"(p));
    return a;
}

static __device__ __forceinline__ uint32_t packbf(float a, float b) {
    __nv_bfloat162 t = __floats2bfloat162_rn(a, b);
    return *reinterpret_cast<uint32_t*>(&t);
}

static __device__ __forceinline__ void split2(float a, float b, uint32_t& hi, uint32_t& lo) {
    float ah = __bfloat162float(__float2bfloat16_rn(a));
    float bh = __bfloat162float(__float2bfloat16_rn(b));
    hi = packbf(a, b);
    lo = packbf(a - ah, b - bh);
}

static __device__ __forceinline__ __nv_bfloat162 u2bf(uint32_t v) {
    return *reinterpret_cast<__nv_bfloat162*>(&v);
}

static __device__ __forceinline__ float tanh_fast(float v) {
    float r;
    asm("tanh.approx.f32 %0, %1;" : "=f"(r) : "f"(v));
    return r;
}

static __device__ __forceinline__ void ldsm_x4(uint32_t* r, uint32_t addr) {
    asm volatile("ldmatrix.sync.aligned.m8n8.x4.shared.b16 {%0,%1,%2,%3}, [%4];"
                 : "=r"(r[0]), "=r"(r[1]), "=r"(r[2]), "=r"(r[3]) : "r"(addr));
}

static __device__ __forceinline__ void ldsm_x4_t(uint32_t* r, uint32_t addr) {
    asm volatile("ldmatrix.sync.aligned.m8n8.x4.trans.shared.b16 {%0,%1,%2,%3}, [%4];"
                 : "=r"(r[0]), "=r"(r[1]), "=r"(r[2]), "=r"(r[3]) : "r"(addr));
}

static __device__ __forceinline__ void mma16816(float* d, const uint32_t* a, const uint32_t* b) {
    asm volatile("mma.sync.aligned.m16n8k16.row.col.f32.bf16.bf16.f32 "
                 "{%0,%1,%2,%3}, {%4,%5,%6,%7}, {%8,%9}, {%0,%1,%2,%3};"
                 : "+f"(d[0]), "+f"(d[1]), "+f"(d[2]), "+f"(d[3])
                 : "r"(a[0]), "r"(a[1]), "r"(a[2]), "r"(a[3]), "r"(b[0]), "r"(b[1]));
}

static __device__ __forceinline__ void pair_bar(int id) {
    asm volatile("bar.sync %0, 64;" :: "r"(id) : "memory");
}

// Warp GEMM: 16 rows (A band in smem, row-major ROW_B) x 64 cols (N-half of W).
static __device__ __forceinline__ void gemm_half(uint32_t abase, uint32_t wbase,
                                                 int lane, float acc[8][4]) {
    uint32_t afr[8][4];
    uint32_t arow = abase + (uint32_t)((lane & 7) + ((lane >> 3) & 1) * 8) * ROW_B
                  + (uint32_t)(lane >> 4) * 16;
    #pragma unroll
    for (int kt = 0; kt < 8; kt++) ldsm_x4(afr[kt], arow + kt * 32);

    uint32_t wl = wbase + (uint32_t)lane * ROW_B;   // + nhalf*128 folded into wbase
    #pragma unroll
    for (int nt = 0; nt < 8; nt++) {
        uint32_t b[4][4];
        #pragma unroll
        for (int q = 0; q < 4; q++)
            ldsm_x4_t(b[q], wl + (uint32_t)q * (32 * ROW_B) + (uint32_t)nt * 16);
        #pragma unroll
        for (int kt = 0; kt < 8; kt++)
            mma16816(acc[nt], afr[kt], &b[kt >> 1][(kt & 1) * 2]);
    }
}

// ---------------- kernel ----------------
__global__ void __launch_bounds__(512, 1)
koopman_persist(const float* __restrict__ x, const float* __restrict__ W1,
                const float* __restrict__ b1, const float* __restrict__ W2,
                const float* __restrict__ b2, float* __restrict__ out)
{
    extern __shared__ char smem[];
    const uint32_t sb = smem_u32(smem);
    const int tid   = threadIdx.x;
    const int lane  = tid & 31;
    const int w     = tid >> 5;         // 0..15
    const int pair  = w >> 1;           // 0..7 : row band
    const int wp    = w & 1;            // warp-in-pair : N half
    const int barid = pair + 1;         // named barriers 1..8

    // ---- one-time: stage W1, W2 (bf16) + biases ----
    #pragma unroll
    for (int j = 0; j < 8; j++) {
        int idx = j * 512 + tid;        // 4096 float4 chunks per matrix
        int r = idx >> 5, c4 = idx & 31;
        float4 wv = *(const float4*)(W1 + (size_t)r * 128 + c4 * 4);
        *(uint2*)(smem + S_W1 + r * ROW_B + c4 * 8) =
            make_uint2(packbf(wv.x, wv.y), packbf(wv.z, wv.w));
        float4 wv2 = *(const float4*)(W2 + (size_t)r * 128 + c4 * 4);
        *(uint2*)(smem + S_W2 + r * ROW_B + c4 * 8) =
            make_uint2(packbf(wv2.x, wv2.y), packbf(wv2.z, wv2.w));
    }
    if (tid < 128) {
        ((float*)(smem + S_B1))[tid] = b1[tid];
        ((float*)(smem + S_B2))[tid] = b2[tid];
    }
    __syncthreads();

    const int g  = lane >> 2;
    const int t2 = (lane & 3) * 2;
    const int band = pair * 16;                       // row band in tile
    const int cbase = wp * 64;                        // N-half col base
    const uint32_t abase_hi = sb + S_AHI + band * ROW_B;
    const uint32_t abase_h  = sb + S_H   + band * ROW_B;
    const uint32_t wb1 = sb + S_W1 + (uint32_t)cbase * 2;
    const uint32_t wb2 = sb + S_W2 + (uint32_t)cbase * 2;
    const float* fb1 = (const float*)(smem + S_B1) + cbase;
    const float* fb2 = (const float*)(smem + S_B2) + cbase;

    for (int t = blockIdx.x; t < NUM_TILES; t += GRID_SMS) {
        const size_t row0 = (size_t)t * 128;

        // ---- stage this pair's 16 x-rows (each warp 8 rows), hi/lo bf16 ----
        {
            int rl0 = band + wp * 8;
            #pragma unroll
            for (int i = 0; i < 8; i++) {
                int rl = rl0 + i;
                float4 v = *(const float4*)(x + (row0 + (size_t)rl) * 128 + lane * 4);
                uint32_t h0, l0, h1, l1;
                split2(v.x, v.y, h0, l0);
                split2(v.z, v.w, h1, l1);
                *(uint2*)(smem + S_AHI + rl * ROW_B + lane * 8) = make_uint2(h0, h1);
                *(uint2*)(smem + S_ALO + rl * ROW_B + lane * 8) = make_uint2(l0, l1);
            }
        }
        pair_bar(barid);

        // ---- GEMM1: pre = Xhi(band) @ W1(:, half) ----
        float acc[8][4];
        #pragma unroll
        for (int i = 0; i < 8; i++)
            { acc[i][0] = 0.f; acc[i][1] = 0.f; acc[i][2] = 0.f; acc[i][3] = 0.f; }
        gemm_half(abase_hi, wb1, lane, acc);

        // ---- epilogue 1: H(band, half) = tanh(pre + b1) ----
        #pragma unroll
        for (int nt = 0; nt < 8; nt++) {
            int cl = nt * 8 + t2;                     // col within half
            float2 bb = *(const float2*)(fb1 + cl);
            int c = cbase + cl;
            uint32_t p0 = packbf(tanh_fast(acc[nt][0] + bb.x), tanh_fast(acc[nt][1] + bb.y));
            uint32_t p1 = packbf(tanh_fast(acc[nt][2] + bb.x), tanh_fast(acc[nt][3] + bb.y));
            *(uint32_t*)(smem + S_H + (band + g) * ROW_B + c * 2) = p0;
            *(uint32_t*)(smem + S_H + (band + g + 8) * ROW_B + c * 2) = p1;
        }
        pair_bar(barid);   // gemm2 A-frags need both halves of H band

        // ---- GEMM2: pre2 = H(band) @ W2(:, half) ----
        #pragma unroll
        for (int i = 0; i < 8; i++)
            { acc[i][0] = 0.f; acc[i][1] = 0.f; acc[i][2] = 0.f; acc[i][3] = 0.f; }
        gemm_half(abase_h, wb2, lane, acc);

        // ---- epilogue 2: rotation-scaling on fp32-reconstructed x ----
        #pragma unroll
        for (int nt = 0; nt < 8; nt++) {
            int cl = nt * 8 + t2;
            float2 bb = *(const float2*)(fb2 + cl);
            int c = cbase + cl;
            #pragma unroll
            for (int half = 0; half < 2; half++) {
                float mu = acc[nt][half * 2 + 0] + bb.x;
                float om = acc[nt][half * 2 + 1] + bb.y;
                int r = band + g + half * 8;
                uint32_t xh = *(const uint32_t*)(smem + S_AHI + r * ROW_B + c * 2);
                uint32_t xl = *(const uint32_t*)(smem + S_ALO + r * ROW_B + c * 2);
                __nv_bfloat162 hh = u2bf(xh), ll = u2bf(xl);
                float xe = __low2float(hh)  + __low2float(ll);
                float xo = __high2float(hh) + __high2float(ll);
                float z  = DT_STEP * mu;
                float e  = fmaf(z, fmaf(z, fmaf(z, 1.f / 6.f, 0.5f), 1.f), 1.f);
                float wv = DT_STEP * om;
                float w2 = wv * wv;
                float s  = wv * fmaf(w2, -1.f / 6.f, 1.f);
                float cc = fmaf(w2, fmaf(w2, 1.f / 24.f, -0.5f), 1.f);
                float2 o;
                o.x = e * (cc * xe - s * xo);
                o.y = e * (s * xe + cc * xo);
                *(float2*)(out + (row0 + (size_t)r) * 128 + c) = o;
            }
        }
        pair_bar(barid);   // protect x/H slices before next-tile staging
    }
}

// ---------------- launch ----------------
extern "C" void kernel_launch(void* const* d_in, const int* in_sizes, int n_in,
                              void* d_out, int out_size) {
    const float* x  = (const float*)d_in[0];
    const float* W1 = (const float*)d_in[1];
    const float* b1 = (const float*)d_in[2];
    const float* W2 = (const float*)d_in[3];
    const float* b2 = (const float*)d_in[4];
    float* out = (float*)d_out;

    cudaFuncSetAttribute(koopman_persist,
                         cudaFuncAttributeMaxDynamicSharedMemorySize, S_TOT);
    koopman_persist<<<GRID_SMS, 512, S_TOT>>>(x, W1, b1, W2, b2, out);
}